// round 14
// baseline (speedup 1.0000x reference)
#include <cuda_runtime.h>
#include <cuda_fp16.h>
#include <cstdint>
#include <math.h>

// ---------------------------------------------------------------- dims
#define B_DIM 8192
#define H_DIM 2048
constexpr int KTOT = 4096;            // folded K: 2048 (x_t) + 2048 (state)

// GEMM tiling (fp16 operands, fp32 accumulate)
constexpr int BM = 128;               // batch rows per CTA
constexpr int BN = 128;               // H cols per CTA (cand & gate both)
constexpr int BK = 32;                // k per stage
constexpr int NSTAGES = 8;
constexpr int NITER = KTOT / BK;      // 128
constexpr int NTHREADS = 256;         // 8 warps: wm = wid&1 (2 along M), wn = wid>>1 (4 along N)

// Tile blob sizes (fragment-ordered, contiguous)
constexpr int A_TILE_BYTES = 8192;    // 128 rows x 32 k x fp16
constexpr int B_TILE_BYTES = 16384;   // (cand 128 + gate 128) cols x 32 k x fp16
constexpr int STAGE_BYTES  = A_TILE_BYTES + B_TILE_BYTES;   // 24576

// smem layout
constexpr int SM_MBAR   = 0;          // 8 x 8B mbarriers
constexpr int SM_STAGE0 = 1024;
constexpr int SMEM_TOTAL = SM_STAGE0 + NSTAGES * STAGE_BYTES;   // 197632

// ---------------------------------------------------------------- scratch (device globals)
// Activations, tiled fragment-order: [rb(64)][ks(128)] -> 8KB blob
__device__ __align__(128) __half g_act[(size_t)64 * 128 * 4096];
// Weights (folded W+U), tiled fragment-order: [cb(16)][ks(128)] -> 16KB blob (Bc 8KB || Bg 8KB)
__device__ __align__(128) __half g_wt [(size_t)16 * 128 * 8192];
__device__ __align__(128) __half g_h16[(size_t)B_DIM * H_DIM];  // h_new (fp16) before layernorm

// ---------------------------------------------------------------- PTX helpers
__device__ __forceinline__ uint32_t smem_u32(const void* p) {
    uint32_t a;
    asm("{ .reg .u64 t; cvta.to.shared.u64 t, %1; cvt.u32.u64 %0, t; }" : "=r"(a) : "l"(p));
    return a;
}
__device__ __forceinline__ void mbar_init(uint32_t a, uint32_t cnt) {
    asm volatile("mbarrier.init.shared.b64 [%0], %1;" :: "r"(a), "r"(cnt) : "memory");
}
__device__ __forceinline__ void mbar_expect_tx(uint32_t a, uint32_t bytes) {
    asm volatile("mbarrier.arrive.expect_tx.shared.b64 _, [%0], %1;"
                 :: "r"(a), "r"(bytes) : "memory");
}
__device__ __forceinline__ void mbar_wait(uint32_t a, uint32_t parity) {
    asm volatile(
        "{\n\t.reg .pred P;\n\t"
        "WL_%=:\n\t"
        "mbarrier.try_wait.parity.acquire.cta.shared::cta.b64 P, [%0], %1, 0x989680;\n\t"
        "@!P bra WL_%=;\n\t}"
        :: "r"(a), "r"(parity) : "memory");
}
__device__ __forceinline__ void bulk_g2s(uint32_t dst_s, const void* src, uint32_t bytes,
                                         uint32_t mbar) {
    asm volatile(
        "cp.async.bulk.shared::cluster.global.mbarrier::complete_tx::bytes [%0], [%1], %2, [%3];"
        :: "r"(dst_s), "l"(src), "r"(bytes), "r"(mbar) : "memory");
}
#define FENCE_PROXY_ASYNC() asm volatile("fence.proxy.async.shared::cta;" ::: "memory")
__device__ __forceinline__ void mma16(float* c, uint32_t a0, uint32_t a1, uint32_t a2, uint32_t a3,
                                      uint32_t b0, uint32_t b1) {
    asm volatile(
        "mma.sync.aligned.m16n8k16.row.col.f32.f16.f16.f32 "
        "{%0,%1,%2,%3}, {%4,%5,%6,%7}, {%8,%9}, {%0,%1,%2,%3};"
        : "+f"(c[0]), "+f"(c[1]), "+f"(c[2]), "+f"(c[3])
        : "r"(a0), "r"(a1), "r"(a2), "r"(a3), "r"(b0), "r"(b1));
}
__device__ __forceinline__ uint32_t packh2(__half lo, __half hi) {
    __half2 p = __halves2half2(lo, hi);
    return *(uint32_t*)&p;
}
__device__ __forceinline__ uint32_t f2h2(float lo, float hi) {
    __half2 p = __floats2half2_rn(lo, hi);
    return *(uint32_t*)&p;
}

// ---------------------------------------------------------------- fused prep
// bid < 8192: activation tile (ks = bid&127, rb = bid>>7) -> 8KB fragment-ordered blob,
//   built DIRECTLY from global (no smem staging):
//   granule gi (16B) = [kk(2)][wm(2)][c(4)][lane(32)]; lane=4g+t4
//   e0,e1 = row r k {2t4,2t4+1}; e2,e3 = row r k {8+2t4,9+2t4}; e4..7 = row r+8 same k
//   r = wm*64 + c*16 + g (k rel. to kk*16)
// bid >= 8192: weight tile (ks = b&127, cb = b>>7) -> 16KB blob: Bc (8KB) then Bg (8KB)
//   granule gi = [kk(2)][wn(4)][cc(2)][lane(32)]; j_lo = wn*32 + cc*16 + g; j_hi = j_lo+8
__global__ void prep_all(const float* __restrict__ x_t, const float* __restrict__ state,
                         const float* __restrict__ Wc, const float* __restrict__ Uc,
                         const float* __restrict__ Wg, const float* __restrict__ Ug) {
    __shared__ __half sm[8192];       // weights only
    const int bid = blockIdx.x;
    const int t = threadIdx.x;

    if (bid < 8192) {
        // ------------- activation tile: direct global -> fragment order -------------
        const int ks = bid & 127, rb = bid >> 7;
        const float* src = (ks < 64) ? x_t : state;
        const int ka = (ks & 63) * 32;

        uint4* dst = (uint4*)(g_act + ((size_t)rb * 128 + ks) * 4096);
        #pragma unroll
        for (int i = 0; i < 2; i++) {
            int gi = t + i * 256;
            int kk = gi >> 8, rem = gi & 255;
            int wm = rem >> 7, c = (rem >> 5) & 3, lane = rem & 31;
            int g = lane >> 2, t4 = lane & 3;
            int r  = rb * 128 + wm * 64 + c * 16 + g;
            int k  = ka + kk * 16 + 2 * t4;
            const float* p0 = src + (size_t)r * H_DIM + k;         // row r,  k-lo
            const float* p1 = src + (size_t)(r + 8) * H_DIM + k;   // row r+8
            float2 aLo = *(const float2*)p0;
            float2 aHi = *(const float2*)(p0 + 8);
            float2 bLo = *(const float2*)p1;
            float2 bHi = *(const float2*)(p1 + 8);
            dst[gi] = make_uint4(f2h2(aLo.x, aLo.y), f2h2(aHi.x, aHi.y),
                                 f2h2(bLo.x, bLo.y), f2h2(bHi.x, bHi.y));
        }
    } else {
        // ------------- weight tile (smem staging: fold + transpose-gather) -------------
        const int b = bid - 8192;
        const int ks = b & 127, cb = b >> 7;
        const int k0 = ks * 32, j0 = cb * 128;
        __half* smc = sm;            // [k(32)][j(128)]
        __half* smg = sm + 4096;

        {   // load 32 k-rows x 128 j, fold U, -> fp16 smem
            int kr = t >> 3, jq = (t & 7) * 16;
            int kg = k0 + kr;
            const float4* wc4 = (const float4*)(Wc + (size_t)kg * H_DIM + j0 + jq);
            const float4* wg4 = (const float4*)(Wg + (size_t)kg * H_DIM + j0 + jq);
            bool fold = (kg >= H_DIM);
            const float4* uc4 = (const float4*)(Uc + (size_t)(kg - H_DIM) * H_DIM + j0 + jq);
            const float4* ug4 = (const float4*)(Ug + (size_t)(kg - H_DIM) * H_DIM + j0 + jq);
            #pragma unroll
            for (int q = 0; q < 4; q++) {
                float4 a = wc4[q], bb = wg4[q];
                if (fold) {
                    float4 u = uc4[q], v = ug4[q];
                    a.x += u.x; a.y += u.y; a.z += u.z; a.w += u.w;
                    bb.x += v.x; bb.y += v.y; bb.z += v.z; bb.w += v.w;
                }
                __half2* dc = (__half2*)&smc[kr * 128 + jq + q * 4];
                __half2* dg = (__half2*)&smg[kr * 128 + jq + q * 4];
                dc[0] = __floats2half2_rn(a.x, a.y);  dc[1] = __floats2half2_rn(a.z, a.w);
                dg[0] = __floats2half2_rn(bb.x, bb.y); dg[1] = __floats2half2_rn(bb.z, bb.w);
            }
        }
        __syncthreads();

        uint4* dst = (uint4*)(g_wt + ((size_t)cb * 128 + ks) * 8192);
        #pragma unroll
        for (int i = 0; i < 4; i++) {
            int gi = t + i * 256;                       // 0..1023
            int m  = gi >> 9, rem = gi & 511;
            int kk = rem >> 8, wn = (rem >> 6) & 3, cc = (rem >> 5) & 1, lane = rem & 31;
            int g = lane >> 2, t4 = lane & 3;
            const __half* s = m ? smg : smc;
            int jlo = wn * 32 + cc * 16 + g;
            int jhi = jlo + 8;
            int kb  = kk * 16 + 2 * t4;
            uint32_t e01 = packh2(s[kb * 128 + jlo],       s[(kb + 1) * 128 + jlo]);
            uint32_t e23 = packh2(s[(kb + 8) * 128 + jlo], s[(kb + 9) * 128 + jlo]);
            uint32_t e45 = packh2(s[kb * 128 + jhi],       s[(kb + 1) * 128 + jhi]);
            uint32_t e67 = packh2(s[(kb + 8) * 128 + jhi], s[(kb + 9) * 128 + jhi]);
            dst[gi] = make_uint4(e01, e23, e45, e67);
        }
    }
}

// ---------------------------------------------------------------- main GEMM
__global__ void __launch_bounds__(NTHREADS, 1)
gemm_kernel(const float* __restrict__ state,
            const float* __restrict__ bc,  const float* __restrict__ bg,
            const float* __restrict__ log_step)
{
    extern __shared__ char smem[];
    const uint32_t sb = smem_u32(smem);
    const int tid = threadIdx.x, wid = tid >> 5, lane = tid & 31;
    const int wm = wid & 1, wn = wid >> 1;
    const int g  = lane >> 2, t4 = lane & 3;
    const int rowBase = blockIdx.y * BM;
    const int colBase = blockIdx.x * BN;

    const __half* actT = g_act + (size_t)blockIdx.y * (128 * 4096);
    const __half* wT   = g_wt  + (size_t)blockIdx.x * (128 * 8192);

    if (tid == 0) {
        for (int s = 0; s < NSTAGES; s++) mbar_init(sb + SM_MBAR + s * 8, 1);
    }
    __syncthreads();

    auto issue = [&](int ks) {
        uint32_t mb  = sb + SM_MBAR + (ks % NSTAGES) * 8;
        uint32_t dst = sb + SM_STAGE0 + (ks % NSTAGES) * STAGE_BYTES;
        mbar_expect_tx(mb, STAGE_BYTES);
        bulk_g2s(dst,                actT + (size_t)ks * 4096, A_TILE_BYTES, mb);
        bulk_g2s(dst + A_TILE_BYTES, wT   + (size_t)ks * 8192, B_TILE_BYTES, mb);
    };

    if (tid == 0) {
        FENCE_PROXY_ASYNC();
        for (int s = 0; s < 6; s++) issue(s);    // 6-deep prologue; pairs keep depth 6-7
    }

    float accC[4][4][4];
    float accG[4][4][4];
    #pragma unroll
    for (int a = 0; a < 4; a++)
        #pragma unroll
        for (int b = 0; b < 4; b++)
            #pragma unroll
            for (int c = 0; c < 4; c++) { accC[a][b][c] = 0.f; accG[a][b][c] = 0.f; }

    auto consume = [&](int kt) {
        const char* st = smem + SM_STAGE0 + (kt % NSTAGES) * STAGE_BYTES;
        #pragma unroll
        for (int kk = 0; kk < 2; kk++) {
            const uint4* pA = (const uint4*)(st + kk * 4096 + wm * 2048 + lane * 16);
            uint4 VA[4];
            #pragma unroll
            for (int c = 0; c < 4; c++) VA[c] = pA[c * 32];      // c stride 512B

            const uint4* pC = (const uint4*)(st + A_TILE_BYTES + kk * 4096
                                             + wn * 1024 + lane * 16);
            const uint4* pG = (const uint4*)(st + A_TILE_BYTES + 8192 + kk * 4096
                                             + wn * 1024 + lane * 16);
            uint4 VC[2], VG[2];
            VC[0] = pC[0]; VC[1] = pC[32];
            VG[0] = pG[0]; VG[1] = pG[32];

            #pragma unroll
            for (int cc = 0; cc < 2; cc++) {
                #pragma unroll
                for (int mt = 0; mt < 4; mt++) {
                    // a0 = row g k-lo, a1 = row g+8 k-lo, a2 = row g k-hi, a3 = row g+8 k-hi
                    mma16(accC[mt][2 * cc],     VA[mt].x, VA[mt].z, VA[mt].y, VA[mt].w,
                          VC[cc].x, VC[cc].y);
                    mma16(accC[mt][2 * cc + 1], VA[mt].x, VA[mt].z, VA[mt].y, VA[mt].w,
                          VC[cc].z, VC[cc].w);
                    mma16(accG[mt][2 * cc],     VA[mt].x, VA[mt].z, VA[mt].y, VA[mt].w,
                          VG[cc].x, VG[cc].y);
                    mma16(accG[mt][2 * cc + 1], VA[mt].x, VA[mt].z, VA[mt].y, VA[mt].w,
                          VG[cc].z, VG[cc].w);
                }
            }
        }
    };

    for (int kt = 0; kt < NITER; kt += 2) {
        __syncthreads();                        // all warps done with pair kt-2,kt-1
        if (tid == 0) {
            FENCE_PROXY_ASYNC();
            if (kt + 6 < NITER) issue(kt + 6);  // slot (kt-2)%8: consumed before sync
            if (kt + 7 < NITER) issue(kt + 7);  // slot (kt-1)%8: consumed before sync
        }
        mbar_wait(sb + SM_MBAR + (kt % NSTAGES) * 8, (uint32_t)((kt >> 3) & 1));
        consume(kt);
        mbar_wait(sb + SM_MBAR + ((kt + 1) % NSTAGES) * 8, (uint32_t)(((kt + 1) >> 3) & 1));
        consume(kt + 1);
    }

    // Epilogue: h = alpha*state + (1-alpha)*sigmoid(zg)*tanh(zc), stored fp16
    #pragma unroll
    for (int nt = 0; nt < 4; nt++) {
        int j0 = colBase + wn * 32 + nt * 8 + 2 * t4;
        float bc0 = bc[j0],  bc1 = bc[j0 + 1];
        float bg0 = bg[j0],  bg1 = bg[j0 + 1];
        float al0 = expf(-expf(-log_step[j0]));      // alpha = exp(-1/exp(log_step))
        float al1 = expf(-expf(-log_step[j0 + 1]));
        #pragma unroll
        for (int mt = 0; mt < 4; mt++) {
            int r0 = rowBase + wm * 64 + mt * 16 + g;
            #pragma unroll
            for (int half = 0; half < 2; half++) {
                int r = r0 + half * 8;
                float zc0 = accC[mt][nt][half * 2]     + bc0;
                float zc1 = accC[mt][nt][half * 2 + 1] + bc1;
                float zg0 = accG[mt][nt][half * 2]     + bg0;
                float zg1 = accG[mt][nt][half * 2 + 1] + bg1;
                float s0 = state[(size_t)r * H_DIM + j0];
                float s1 = state[(size_t)r * H_DIM + j0 + 1];
                float cand0 = tanhf(zc0), cand1 = tanhf(zc1);
                float gate0 = 1.f / (1.f + expf(-zg0));
                float gate1 = 1.f / (1.f + expf(-zg1));
                float h0 = al0 * s0 + (1.f - al0) * gate0 * cand0;
                float h1 = al1 * s1 + (1.f - al1) * gate1 * cand1;
                *(__half2*)&g_h16[(size_t)r * H_DIM + j0] = __floats2half2_rn(h0, h1);
            }
        }
    }
}

// ---------------------------------------------------------------- layernorm over H=2048 (fp16 in, fp32 out)
__device__ __forceinline__ float warp_sum(float v) {
    #pragma unroll
    for (int o = 16; o; o >>= 1) v += __shfl_xor_sync(0xffffffffu, v, o);
    return v;
}

__global__ void ln_kernel(const float* __restrict__ gamma, const float* __restrict__ beta,
                          float* __restrict__ out)
{
    int row = blockIdx.x;
    int tid = threadIdx.x;                       // 256 threads, 8 halves each

    uint4 v = ((const uint4*)(g_h16 + (size_t)row * H_DIM))[tid];
    const __half2* hp = (const __half2*)&v;
    float f[8];
    #pragma unroll
    for (int i = 0; i < 4; i++) {
        float2 p = __half22float2(hp[i]);
        f[2 * i] = p.x; f[2 * i + 1] = p.y;
    }

    float s = 0.f, sq = 0.f;
    #pragma unroll
    for (int i = 0; i < 8; i++) { s += f[i]; sq += f[i] * f[i]; }

    s  = warp_sum(s);
    sq = warp_sum(sq);
    __shared__ float sh[16];
    int wid = tid >> 5, lane = tid & 31;
    if (lane == 0) { sh[wid] = s; sh[8 + wid] = sq; }
    __syncthreads();
    float tot = 0.f, totq = 0.f;
    #pragma unroll
    for (int i = 0; i < 8; i++) { tot += sh[i]; totq += sh[8 + i]; }

    float mu  = tot * (1.f / H_DIM);
    float var = totq * (1.f / H_DIM) - mu * mu;
    float inv = rsqrtf(var + 1e-5f);

    const float4* gm = (const float4*)(gamma + tid * 8);
    const float4* bt = (const float4*)(beta  + tid * 8);
    float4* o = (float4*)(out + (size_t)row * H_DIM + tid * 8);
    #pragma unroll
    for (int q = 0; q < 2; q++) {
        float4 gv = gm[q], bv = bt[q], ov;
        ov.x = (f[4 * q]     - mu) * inv * gv.x + bv.x;
        ov.y = (f[4 * q + 1] - mu) * inv * gv.y + bv.y;
        ov.z = (f[4 * q + 2] - mu) * inv * gv.z + bv.z;
        ov.w = (f[4 * q + 3] - mu) * inv * gv.w + bv.w;
        o[q] = ov;
    }
}

// ---------------------------------------------------------------- launch
extern "C" void kernel_launch(void* const* d_in, const int* in_sizes, int n_in,
                              void* d_out, int out_size) {
    const float* x_t      = (const float*)d_in[0];
    const float* state    = (const float*)d_in[1];
    const float* Wc       = (const float*)d_in[2];
    const float* Uc       = (const float*)d_in[3];
    const float* bc       = (const float*)d_in[4];
    const float* Wg       = (const float*)d_in[5];
    const float* Ug       = (const float*)d_in[6];
    const float* bg       = (const float*)d_in[7];
    const float* log_step = (const float*)d_in[8];
    const float* gamma    = (const float*)d_in[9];
    const float* beta     = (const float*)d_in[10];
    float* out = (float*)d_out;

    cudaFuncSetAttribute(gemm_kernel, cudaFuncAttributeMaxDynamicSharedMemorySize, SMEM_TOTAL);

    prep_all<<<8192 + 2048, 256>>>(x_t, state, Wc, Uc, Wg, Ug);

    dim3 grid(H_DIM / BN, B_DIM / BM);     // (16, 64) = 1024 CTAs
    gemm_kernel<<<grid, NTHREADS, SMEM_TOTAL>>>(state, bc, bg, log_step);

    ln_kernel<<<B_DIM, 256>>>(gamma, beta, out);
}

// round 15
// speedup vs baseline: 1.0697x; 1.0697x over previous
#include <cuda_runtime.h>
#include <cuda_fp16.h>
#include <cstdint>
#include <math.h>

// ---------------------------------------------------------------- dims
#define B_DIM 8192
#define H_DIM 2048
constexpr int KTOT = 4096;            // folded K: 2048 (x_t) + 2048 (state)

// GEMM tiling (fp16 operands, fp32 accumulate)
constexpr int BM = 128;               // batch rows per CTA
constexpr int BN = 128;               // H cols per CTA (cand & gate both)
constexpr int BK = 32;                // k per stage
constexpr int NSTAGES = 8;
constexpr int NITER = KTOT / BK;      // 128
constexpr int NTHREADS = 512;         // 16 warps: wm = wid&3 (4 along M), wn = wid>>2 (4 along N)

// Tile blob sizes (fragment-ordered, contiguous)
constexpr int A_TILE_BYTES = 8192;    // 128 rows x 32 k x fp16
constexpr int B_TILE_BYTES = 16384;   // (cand 128 + gate 128) cols x 32 k x fp16
constexpr int STAGE_BYTES  = A_TILE_BYTES + B_TILE_BYTES;   // 24576

// smem layout
constexpr int SM_MBAR   = 0;          // 8 x 8B mbarriers
constexpr int SM_STAGE0 = 1024;
constexpr int SMEM_TOTAL = SM_STAGE0 + NSTAGES * STAGE_BYTES;   // 197632

// ---------------------------------------------------------------- scratch (device globals)
// Activations, tiled fragment-order: [rb(64)][ks(128)] -> 8KB blob
__device__ __align__(128) __half g_act[(size_t)64 * 128 * 4096];
// Weights (folded W+U), tiled fragment-order: [cb(16)][ks(128)] -> 16KB blob (Bc 8KB || Bg 8KB)
__device__ __align__(128) __half g_wt [(size_t)16 * 128 * 8192];
__device__ __align__(128) __half g_h16[(size_t)B_DIM * H_DIM];  // h_new (fp16) before layernorm

// ---------------------------------------------------------------- PTX helpers
__device__ __forceinline__ uint32_t smem_u32(const void* p) {
    uint32_t a;
    asm("{ .reg .u64 t; cvta.to.shared.u64 t, %1; cvt.u32.u64 %0, t; }" : "=r"(a) : "l"(p));
    return a;
}
__device__ __forceinline__ void mbar_init(uint32_t a, uint32_t cnt) {
    asm volatile("mbarrier.init.shared.b64 [%0], %1;" :: "r"(a), "r"(cnt) : "memory");
}
__device__ __forceinline__ void mbar_expect_tx(uint32_t a, uint32_t bytes) {
    asm volatile("mbarrier.arrive.expect_tx.shared.b64 _, [%0], %1;"
                 :: "r"(a), "r"(bytes) : "memory");
}
__device__ __forceinline__ void mbar_wait(uint32_t a, uint32_t parity) {
    asm volatile(
        "{\n\t.reg .pred P;\n\t"
        "WL_%=:\n\t"
        "mbarrier.try_wait.parity.acquire.cta.shared::cta.b64 P, [%0], %1, 0x989680;\n\t"
        "@!P bra WL_%=;\n\t}"
        :: "r"(a), "r"(parity) : "memory");
}
__device__ __forceinline__ void bulk_g2s(uint32_t dst_s, const void* src, uint32_t bytes,
                                         uint32_t mbar) {
    asm volatile(
        "cp.async.bulk.shared::cluster.global.mbarrier::complete_tx::bytes [%0], [%1], %2, [%3];"
        :: "r"(dst_s), "l"(src), "r"(bytes), "r"(mbar) : "memory");
}
#define FENCE_PROXY_ASYNC() asm volatile("fence.proxy.async.shared::cta;" ::: "memory")
__device__ __forceinline__ void mma16(float* c, uint32_t a0, uint32_t a1, uint32_t a2, uint32_t a3,
                                      uint32_t b0, uint32_t b1) {
    asm volatile(
        "mma.sync.aligned.m16n8k16.row.col.f32.f16.f16.f32 "
        "{%0,%1,%2,%3}, {%4,%5,%6,%7}, {%8,%9}, {%0,%1,%2,%3};"
        : "+f"(c[0]), "+f"(c[1]), "+f"(c[2]), "+f"(c[3])
        : "r"(a0), "r"(a1), "r"(a2), "r"(a3), "r"(b0), "r"(b1));
}
__device__ __forceinline__ uint32_t packh2(__half lo, __half hi) {
    __half2 p = __halves2half2(lo, hi);
    return *(uint32_t*)&p;
}
__device__ __forceinline__ uint32_t f2h2(float lo, float hi) {
    __half2 p = __floats2half2_rn(lo, hi);
    return *(uint32_t*)&p;
}

// ---------------------------------------------------------------- fused prep
// bid < 8192: activation tile (ks = bid&127, rb = bid>>7) -> 8KB fragment-ordered blob,
//   built DIRECTLY from global (no smem staging):
//   granule gi (16B) = [kk(2)][blk(8)][lane(32)]; lane=4g+t4; blk = row/16
//   e0,e1 = row r k {2t4,2t4+1}; e2,e3 = row r k {8+2t4,9+2t4}; e4..7 = row r+8 same k
//   r = blk*16 + g (k rel. to kk*16)
// bid >= 8192: weight tile (ks = b&127, cb = b>>7) -> 16KB blob: Bc (8KB) then Bg (8KB)
//   granule gi = [kk(2)][wn(4)][cc(2)][lane(32)]; j_lo = wn*32 + cc*16 + g; j_hi = j_lo+8
__global__ void prep_all(const float* __restrict__ x_t, const float* __restrict__ state,
                         const float* __restrict__ Wc, const float* __restrict__ Uc,
                         const float* __restrict__ Wg, const float* __restrict__ Ug) {
    __shared__ __half sm[8192];       // weights only
    const int bid = blockIdx.x;
    const int t = threadIdx.x;

    if (bid < 8192) {
        // ------------- activation tile: direct global -> fragment order -------------
        const int ks = bid & 127, rb = bid >> 7;
        const float* src = (ks < 64) ? x_t : state;
        const int ka = (ks & 63) * 32;

        uint4* dst = (uint4*)(g_act + ((size_t)rb * 128 + ks) * 4096);
        #pragma unroll
        for (int i = 0; i < 2; i++) {
            int gi = t + i * 256;
            int kk = gi >> 8, rem = gi & 255;
            int blk = rem >> 5, lane = rem & 31;
            int g = lane >> 2, t4 = lane & 3;
            int r  = rb * 128 + blk * 16 + g;
            int k  = ka + kk * 16 + 2 * t4;
            const float* p0 = src + (size_t)r * H_DIM + k;         // row r,  k-lo
            const float* p1 = src + (size_t)(r + 8) * H_DIM + k;   // row r+8
            float2 aLo = *(const float2*)p0;
            float2 aHi = *(const float2*)(p0 + 8);
            float2 bLo = *(const float2*)p1;
            float2 bHi = *(const float2*)(p1 + 8);
            dst[gi] = make_uint4(f2h2(aLo.x, aLo.y), f2h2(aHi.x, aHi.y),
                                 f2h2(bLo.x, bLo.y), f2h2(bHi.x, bHi.y));
        }
    } else {
        // ------------- weight tile (smem staging: fold + transpose-gather) -------------
        const int b = bid - 8192;
        const int ks = b & 127, cb = b >> 7;
        const int k0 = ks * 32, j0 = cb * 128;
        __half* smc = sm;            // [k(32)][j(128)]
        __half* smg = sm + 4096;

        {   // load 32 k-rows x 128 j, fold U, -> fp16 smem
            int kr = t >> 3, jq = (t & 7) * 16;
            int kg = k0 + kr;
            const float4* wc4 = (const float4*)(Wc + (size_t)kg * H_DIM + j0 + jq);
            const float4* wg4 = (const float4*)(Wg + (size_t)kg * H_DIM + j0 + jq);
            bool fold = (kg >= H_DIM);
            const float4* uc4 = (const float4*)(Uc + (size_t)(kg - H_DIM) * H_DIM + j0 + jq);
            const float4* ug4 = (const float4*)(Ug + (size_t)(kg - H_DIM) * H_DIM + j0 + jq);
            #pragma unroll
            for (int q = 0; q < 4; q++) {
                float4 a = wc4[q], bb = wg4[q];
                if (fold) {
                    float4 u = uc4[q], v = ug4[q];
                    a.x += u.x; a.y += u.y; a.z += u.z; a.w += u.w;
                    bb.x += v.x; bb.y += v.y; bb.z += v.z; bb.w += v.w;
                }
                __half2* dc = (__half2*)&smc[kr * 128 + jq + q * 4];
                __half2* dg = (__half2*)&smg[kr * 128 + jq + q * 4];
                dc[0] = __floats2half2_rn(a.x, a.y);  dc[1] = __floats2half2_rn(a.z, a.w);
                dg[0] = __floats2half2_rn(bb.x, bb.y); dg[1] = __floats2half2_rn(bb.z, bb.w);
            }
        }
        __syncthreads();

        uint4* dst = (uint4*)(g_wt + ((size_t)cb * 128 + ks) * 8192);
        #pragma unroll
        for (int i = 0; i < 4; i++) {
            int gi = t + i * 256;                       // 0..1023
            int m  = gi >> 9, rem = gi & 511;
            int kk = rem >> 8, wn = (rem >> 6) & 3, cc = (rem >> 5) & 1, lane = rem & 31;
            int g = lane >> 2, t4 = lane & 3;
            const __half* s = m ? smg : smc;
            int jlo = wn * 32 + cc * 16 + g;
            int jhi = jlo + 8;
            int kb  = kk * 16 + 2 * t4;
            uint32_t e01 = packh2(s[kb * 128 + jlo],       s[(kb + 1) * 128 + jlo]);
            uint32_t e23 = packh2(s[(kb + 8) * 128 + jlo], s[(kb + 9) * 128 + jlo]);
            uint32_t e45 = packh2(s[kb * 128 + jhi],       s[(kb + 1) * 128 + jhi]);
            uint32_t e67 = packh2(s[(kb + 8) * 128 + jhi], s[(kb + 9) * 128 + jhi]);
            dst[gi] = make_uint4(e01, e23, e45, e67);
        }
    }
}

// ---------------------------------------------------------------- main GEMM (16 warps)
__global__ void __launch_bounds__(NTHREADS, 1)
gemm_kernel(const float* __restrict__ state,
            const float* __restrict__ bc,  const float* __restrict__ bg,
            const float* __restrict__ log_step)
{
    extern __shared__ char smem[];
    const uint32_t sb = smem_u32(smem);
    const int tid = threadIdx.x, wid = tid >> 5, lane = tid & 31;
    const int wm = wid & 3, wn = wid >> 2;      // 4 along M x 4 along N; warp tile 32x32 (C & G)
    const int g  = lane >> 2, t4 = lane & 3;
    const int rowBase = blockIdx.y * BM;
    const int colBase = blockIdx.x * BN;

    const __half* actT = g_act + (size_t)blockIdx.y * (128 * 4096);
    const __half* wT   = g_wt  + (size_t)blockIdx.x * (128 * 8192);

    if (tid == 0) {
        for (int s = 0; s < NSTAGES; s++) mbar_init(sb + SM_MBAR + s * 8, 1);
    }
    __syncthreads();

    auto issue = [&](int ks) {
        uint32_t mb  = sb + SM_MBAR + (ks % NSTAGES) * 8;
        uint32_t dst = sb + SM_STAGE0 + (ks % NSTAGES) * STAGE_BYTES;
        mbar_expect_tx(mb, STAGE_BYTES);
        bulk_g2s(dst,                actT + (size_t)ks * 4096, A_TILE_BYTES, mb);
        bulk_g2s(dst + A_TILE_BYTES, wT   + (size_t)ks * 8192, B_TILE_BYTES, mb);
    };

    if (tid == 0) {
        FENCE_PROXY_ASYNC();
        for (int s = 0; s < 6; s++) issue(s);    // 6-deep prologue; pairs keep depth 6-7
    }

    float accC[2][4][4];     // [mt][nt][frag]
    float accG[2][4][4];
    #pragma unroll
    for (int a = 0; a < 2; a++)
        #pragma unroll
        for (int b = 0; b < 4; b++)
            #pragma unroll
            for (int c = 0; c < 4; c++) { accC[a][b][c] = 0.f; accG[a][b][c] = 0.f; }

    auto consume = [&](int kt) {
        const char* st = smem + SM_STAGE0 + (kt % NSTAGES) * STAGE_BYTES;
        #pragma unroll
        for (int kk = 0; kk < 2; kk++) {
            // A: 16-row blocks wm*2 + mt, each block = 32 granules (512B)
            const uint4* pA = (const uint4*)(st + kk * 4096 + wm * 1024 + lane * 16);
            uint4 VA[2];
            VA[0] = pA[0]; VA[1] = pA[32];

            const uint4* pC = (const uint4*)(st + A_TILE_BYTES + kk * 4096
                                             + wn * 1024 + lane * 16);
            const uint4* pG = (const uint4*)(st + A_TILE_BYTES + 8192 + kk * 4096
                                             + wn * 1024 + lane * 16);
            uint4 VC[2], VG[2];
            VC[0] = pC[0]; VC[1] = pC[32];
            VG[0] = pG[0]; VG[1] = pG[32];

            #pragma unroll
            for (int cc = 0; cc < 2; cc++) {
                #pragma unroll
                for (int mt = 0; mt < 2; mt++) {
                    // a0 = row g k-lo, a1 = row g+8 k-lo, a2 = row g k-hi, a3 = row g+8 k-hi
                    mma16(accC[mt][2 * cc],     VA[mt].x, VA[mt].z, VA[mt].y, VA[mt].w,
                          VC[cc].x, VC[cc].y);
                    mma16(accC[mt][2 * cc + 1], VA[mt].x, VA[mt].z, VA[mt].y, VA[mt].w,
                          VC[cc].z, VC[cc].w);
                    mma16(accG[mt][2 * cc],     VA[mt].x, VA[mt].z, VA[mt].y, VA[mt].w,
                          VG[cc].x, VG[cc].y);
                    mma16(accG[mt][2 * cc + 1], VA[mt].x, VA[mt].z, VA[mt].y, VA[mt].w,
                          VG[cc].z, VG[cc].w);
                }
            }
        }
    };

    for (int kt = 0; kt < NITER; kt += 2) {
        __syncthreads();                        // all warps done with pair kt-2,kt-1
        if (tid == 0) {
            FENCE_PROXY_ASYNC();
            if (kt + 6 < NITER) issue(kt + 6);  // slot (kt-2)%8: consumed before sync
            if (kt + 7 < NITER) issue(kt + 7);  // slot (kt-1)%8: consumed before sync
        }
        mbar_wait(sb + SM_MBAR + (kt % NSTAGES) * 8, (uint32_t)((kt >> 3) & 1));
        consume(kt);
        mbar_wait(sb + SM_MBAR + ((kt + 1) % NSTAGES) * 8, (uint32_t)(((kt + 1) >> 3) & 1));
        consume(kt + 1);
    }

    // Epilogue: h = alpha*state + (1-alpha)*sigmoid(zg)*tanh(zc), stored fp16
    #pragma unroll
    for (int nt = 0; nt < 4; nt++) {
        int j0 = colBase + wn * 32 + nt * 8 + 2 * t4;
        float bc0 = bc[j0],  bc1 = bc[j0 + 1];
        float bg0 = bg[j0],  bg1 = bg[j0 + 1];
        float al0 = expf(-expf(-log_step[j0]));      // alpha = exp(-1/exp(log_step))
        float al1 = expf(-expf(-log_step[j0 + 1]));
        #pragma unroll
        for (int mt = 0; mt < 2; mt++) {
            int r0 = rowBase + wm * 32 + mt * 16 + g;
            #pragma unroll
            for (int half = 0; half < 2; half++) {
                int r = r0 + half * 8;
                float zc0 = accC[mt][nt][half * 2]     + bc0;
                float zc1 = accC[mt][nt][half * 2 + 1] + bc1;
                float zg0 = accG[mt][nt][half * 2]     + bg0;
                float zg1 = accG[mt][nt][half * 2 + 1] + bg1;
                float s0 = state[(size_t)r * H_DIM + j0];
                float s1 = state[(size_t)r * H_DIM + j0 + 1];
                float cand0 = tanhf(zc0), cand1 = tanhf(zc1);
                float gate0 = 1.f / (1.f + expf(-zg0));
                float gate1 = 1.f / (1.f + expf(-zg1));
                float h0 = al0 * s0 + (1.f - al0) * gate0 * cand0;
                float h1 = al1 * s1 + (1.f - al1) * gate1 * cand1;
                *(__half2*)&g_h16[(size_t)r * H_DIM + j0] = __floats2half2_rn(h0, h1);
            }
        }
    }
}

// ---------------------------------------------------------------- layernorm over H=2048 (fp16 in, fp32 out)
__device__ __forceinline__ float warp_sum(float v) {
    #pragma unroll
    for (int o = 16; o; o >>= 1) v += __shfl_xor_sync(0xffffffffu, v, o);
    return v;
}

__global__ void ln_kernel(const float* __restrict__ gamma, const float* __restrict__ beta,
                          float* __restrict__ out)
{
    int row = blockIdx.x;
    int tid = threadIdx.x;                       // 256 threads, 8 halves each

    uint4 v = ((const uint4*)(g_h16 + (size_t)row * H_DIM))[tid];
    const __half2* hp = (const __half2*)&v;
    float f[8];
    #pragma unroll
    for (int i = 0; i < 4; i++) {
        float2 p = __half22float2(hp[i]);
        f[2 * i] = p.x; f[2 * i + 1] = p.y;
    }

    float s = 0.f, sq = 0.f;
    #pragma unroll
    for (int i = 0; i < 8; i++) { s += f[i]; sq += f[i] * f[i]; }

    s  = warp_sum(s);
    sq = warp_sum(sq);
    __shared__ float sh[16];
    int wid = tid >> 5, lane = tid & 31;
    if (lane == 0) { sh[wid] = s; sh[8 + wid] = sq; }
    __syncthreads();
    float tot = 0.f, totq = 0.f;
    #pragma unroll
    for (int i = 0; i < 8; i++) { tot += sh[i]; totq += sh[8 + i]; }

    float mu  = tot * (1.f / H_DIM);
    float var = totq * (1.f / H_DIM) - mu * mu;
    float inv = rsqrtf(var + 1e-5f);

    const float4* gm = (const float4*)(gamma + tid * 8);
    const float4* bt = (const float4*)(beta  + tid * 8);
    float4* o = (float4*)(out + (size_t)row * H_DIM + tid * 8);
    #pragma unroll
    for (int q = 0; q < 2; q++) {
        float4 gv = gm[q], bv = bt[q], ov;
        ov.x = (f[4 * q]     - mu) * inv * gv.x + bv.x;
        ov.y = (f[4 * q + 1] - mu) * inv * gv.y + bv.y;
        ov.z = (f[4 * q + 2] - mu) * inv * gv.z + bv.z;
        ov.w = (f[4 * q + 3] - mu) * inv * gv.w + bv.w;
        o[q] = ov;
    }
}

// ---------------------------------------------------------------- launch
extern "C" void kernel_launch(void* const* d_in, const int* in_sizes, int n_in,
                              void* d_out, int out_size) {
    const float* x_t      = (const float*)d_in[0];
    const float* state    = (const float*)d_in[1];
    const float* Wc       = (const float*)d_in[2];
    const float* Uc       = (const float*)d_in[3];
    const float* bc       = (const float*)d_in[4];
    const float* Wg       = (const float*)d_in[5];
    const float* Ug       = (const float*)d_in[6];
    const float* bg       = (const float*)d_in[7];
    const float* log_step = (const float*)d_in[8];
    const float* gamma    = (const float*)d_in[9];
    const float* beta     = (const float*)d_in[10];
    float* out = (float*)d_out;

    cudaFuncSetAttribute(gemm_kernel, cudaFuncAttributeMaxDynamicSharedMemorySize, SMEM_TOTAL);

    prep_all<<<8192 + 2048, 256>>>(x_t, state, Wc, Uc, Wg, Ug);

    dim3 grid(H_DIM / BN, B_DIM / BM);     // (16, 64) = 1024 CTAs
    gemm_kernel<<<grid, NTHREADS, SMEM_TOTAL>>>(state, bc, bg, log_step);

    ln_kernel<<<B_DIM, 256>>>(gamma, beta, out);
}

// round 16
// speedup vs baseline: 1.0836x; 1.0130x over previous
#include <cuda_runtime.h>
#include <cuda_fp16.h>
#include <cstdint>
#include <math.h>

// ---------------------------------------------------------------- dims
#define B_DIM 8192
#define H_DIM 2048
constexpr int KTOT = 4096;            // folded K: 2048 (x_t) + 2048 (state)

// GEMM tiling (fp16 operands, fp32 accumulate)
constexpr int BM = 128;               // batch rows per CTA
constexpr int BN = 128;               // H cols per CTA (cand & gate both)
constexpr int BK = 32;                // k per stage
constexpr int NSTAGES = 8;
constexpr int NITER = KTOT / BK;      // 128
constexpr int NTHREADS = 512;         // 16 warps: wm = wid&3 (4 along M), wn = wid>>2 (4 along N)

// Tile blob sizes (fragment-ordered, contiguous)
constexpr int A_TILE_BYTES = 8192;    // 128 rows x 32 k x fp16
constexpr int B_TILE_BYTES = 16384;   // (cand 128 + gate 128) cols x 32 k x fp16
constexpr int STAGE_BYTES  = A_TILE_BYTES + B_TILE_BYTES;   // 24576

// smem layout
constexpr int SM_MBAR   = 0;          // 8 x 8B mbarriers
constexpr int SM_STAGE0 = 1024;
constexpr int SMEM_TOTAL = SM_STAGE0 + NSTAGES * STAGE_BYTES;   // 197632

// ---------------------------------------------------------------- scratch (device globals)
// Activations, tiled fragment-order: [rb(64)][ks(128)] -> 8KB blob
__device__ __align__(128) __half g_act[(size_t)64 * 128 * 4096];
// Weights (folded W+U), tiled fragment-order: [cb(16)][ks(128)] -> 16KB blob (Bc 8KB || Bg 8KB)
__device__ __align__(128) __half g_wt [(size_t)16 * 128 * 8192];
__device__ __align__(128) __half g_h16[(size_t)B_DIM * H_DIM];  // h_new (fp16) before layernorm

// ---------------------------------------------------------------- PTX helpers
__device__ __forceinline__ uint32_t smem_u32(const void* p) {
    uint32_t a;
    asm("{ .reg .u64 t; cvta.to.shared.u64 t, %1; cvt.u32.u64 %0, t; }" : "=r"(a) : "l"(p));
    return a;
}
__device__ __forceinline__ void mbar_init(uint32_t a, uint32_t cnt) {
    asm volatile("mbarrier.init.shared.b64 [%0], %1;" :: "r"(a), "r"(cnt) : "memory");
}
__device__ __forceinline__ void mbar_expect_tx(uint32_t a, uint32_t bytes) {
    asm volatile("mbarrier.arrive.expect_tx.shared.b64 _, [%0], %1;"
                 :: "r"(a), "r"(bytes) : "memory");
}
__device__ __forceinline__ void mbar_wait(uint32_t a, uint32_t parity) {
    asm volatile(
        "{\n\t.reg .pred P;\n\t"
        "WL_%=:\n\t"
        "mbarrier.try_wait.parity.acquire.cta.shared::cta.b64 P, [%0], %1, 0x989680;\n\t"
        "@!P bra WL_%=;\n\t}"
        :: "r"(a), "r"(parity) : "memory");
}
__device__ __forceinline__ void bulk_g2s(uint32_t dst_s, const void* src, uint32_t bytes,
                                         uint32_t mbar) {
    asm volatile(
        "cp.async.bulk.shared::cluster.global.mbarrier::complete_tx::bytes [%0], [%1], %2, [%3];"
        :: "r"(dst_s), "l"(src), "r"(bytes), "r"(mbar) : "memory");
}
#define FENCE_PROXY_ASYNC() asm volatile("fence.proxy.async.shared::cta;" ::: "memory")
__device__ __forceinline__ void mma16(float* c, uint32_t a0, uint32_t a1, uint32_t a2, uint32_t a3,
                                      uint32_t b0, uint32_t b1) {
    asm volatile(
        "mma.sync.aligned.m16n8k16.row.col.f32.f16.f16.f32 "
        "{%0,%1,%2,%3}, {%4,%5,%6,%7}, {%8,%9}, {%0,%1,%2,%3};"
        : "+f"(c[0]), "+f"(c[1]), "+f"(c[2]), "+f"(c[3])
        : "r"(a0), "r"(a1), "r"(a2), "r"(a3), "r"(b0), "r"(b1));
}
__device__ __forceinline__ uint32_t packh2(__half lo, __half hi) {
    __half2 p = __halves2half2(lo, hi);
    return *(uint32_t*)&p;
}
__device__ __forceinline__ uint32_t f2h2(float lo, float hi) {
    __half2 p = __floats2half2_rn(lo, hi);
    return *(uint32_t*)&p;
}

// ---------------------------------------------------------------- fused prep
// bid < 8192: activation tile (ks = bid&127, rb = bid>>7) -> 8KB fragment-ordered blob,
//   built DIRECTLY from global (no smem staging):
//   granule gi (16B) = [kk(2)][blk(8)][lane(32)]; lane=4g+t4; blk = row/16
//   e0,e1 = row r k {2t4,2t4+1}; e2,e3 = row r k {8+2t4,9+2t4}; e4..7 = row r+8 same k
//   r = blk*16 + g (k rel. to kk*16)
// bid >= 8192: weight tile (ks = b&127, cb = b>>7) -> 16KB blob: Bc (8KB) then Bg (8KB)
//   granule gi = [kk(2)][wn(4)][cc(2)][lane(32)]; j_lo = wn*32 + cc*16 + g; j_hi = j_lo+8
__global__ void prep_all(const float* __restrict__ x_t, const float* __restrict__ state,
                         const float* __restrict__ Wc, const float* __restrict__ Uc,
                         const float* __restrict__ Wg, const float* __restrict__ Ug) {
    __shared__ __half sm[8192];       // weights only
    const int bid = blockIdx.x;
    const int t = threadIdx.x;

    if (bid < 8192) {
        // ------------- activation tile: direct global -> fragment order -------------
        const int ks = bid & 127, rb = bid >> 7;
        const float* src = (ks < 64) ? x_t : state;
        const int ka = (ks & 63) * 32;

        uint4* dst = (uint4*)(g_act + ((size_t)rb * 128 + ks) * 4096);
        #pragma unroll
        for (int i = 0; i < 2; i++) {
            int gi = t + i * 256;
            int kk = gi >> 8, rem = gi & 255;
            int blk = rem >> 5, lane = rem & 31;
            int g = lane >> 2, t4 = lane & 3;
            int r  = rb * 128 + blk * 16 + g;
            int k  = ka + kk * 16 + 2 * t4;
            const float* p0 = src + (size_t)r * H_DIM + k;         // row r,  k-lo
            const float* p1 = src + (size_t)(r + 8) * H_DIM + k;   // row r+8
            float2 aLo = *(const float2*)p0;
            float2 aHi = *(const float2*)(p0 + 8);
            float2 bLo = *(const float2*)p1;
            float2 bHi = *(const float2*)(p1 + 8);
            dst[gi] = make_uint4(f2h2(aLo.x, aLo.y), f2h2(aHi.x, aHi.y),
                                 f2h2(bLo.x, bLo.y), f2h2(bHi.x, bHi.y));
        }
    } else {
        // ------------- weight tile (smem staging: fold + transpose-gather) -------------
        const int b = bid - 8192;
        const int ks = b & 127, cb = b >> 7;
        const int k0 = ks * 32, j0 = cb * 128;
        __half* smc = sm;            // [k(32)][j(128)]
        __half* smg = sm + 4096;

        {   // load 32 k-rows x 128 j, fold U, -> fp16 smem
            int kr = t >> 3, jq = (t & 7) * 16;
            int kg = k0 + kr;
            const float4* wc4 = (const float4*)(Wc + (size_t)kg * H_DIM + j0 + jq);
            const float4* wg4 = (const float4*)(Wg + (size_t)kg * H_DIM + j0 + jq);
            bool fold = (kg >= H_DIM);
            const float4* uc4 = (const float4*)(Uc + (size_t)(kg - H_DIM) * H_DIM + j0 + jq);
            const float4* ug4 = (const float4*)(Ug + (size_t)(kg - H_DIM) * H_DIM + j0 + jq);
            #pragma unroll
            for (int q = 0; q < 4; q++) {
                float4 a = wc4[q], bb = wg4[q];
                if (fold) {
                    float4 u = uc4[q], v = ug4[q];
                    a.x += u.x; a.y += u.y; a.z += u.z; a.w += u.w;
                    bb.x += v.x; bb.y += v.y; bb.z += v.z; bb.w += v.w;
                }
                __half2* dc = (__half2*)&smc[kr * 128 + jq + q * 4];
                __half2* dg = (__half2*)&smg[kr * 128 + jq + q * 4];
                dc[0] = __floats2half2_rn(a.x, a.y);  dc[1] = __floats2half2_rn(a.z, a.w);
                dg[0] = __floats2half2_rn(bb.x, bb.y); dg[1] = __floats2half2_rn(bb.z, bb.w);
            }
        }
        __syncthreads();

        uint4* dst = (uint4*)(g_wt + ((size_t)cb * 128 + ks) * 8192);
        #pragma unroll
        for (int i = 0; i < 4; i++) {
            int gi = t + i * 256;                       // 0..1023
            int m  = gi >> 9, rem = gi & 511;
            int kk = rem >> 8, wn = (rem >> 6) & 3, cc = (rem >> 5) & 1, lane = rem & 31;
            int g = lane >> 2, t4 = lane & 3;
            const __half* s = m ? smg : smc;
            int jlo = wn * 32 + cc * 16 + g;
            int jhi = jlo + 8;
            int kb  = kk * 16 + 2 * t4;
            uint32_t e01 = packh2(s[kb * 128 + jlo],       s[(kb + 1) * 128 + jlo]);
            uint32_t e23 = packh2(s[(kb + 8) * 128 + jlo], s[(kb + 9) * 128 + jlo]);
            uint32_t e45 = packh2(s[kb * 128 + jhi],       s[(kb + 1) * 128 + jhi]);
            uint32_t e67 = packh2(s[(kb + 8) * 128 + jhi], s[(kb + 9) * 128 + jhi]);
            dst[gi] = make_uint4(e01, e23, e45, e67);
        }
    }
}

// ---------------------------------------------------------------- main GEMM (16 warps, quad-batched)
__global__ void __launch_bounds__(NTHREADS, 1)
gemm_kernel(const float* __restrict__ state,
            const float* __restrict__ bc,  const float* __restrict__ bg,
            const float* __restrict__ log_step)
{
    extern __shared__ char smem[];
    const uint32_t sb = smem_u32(smem);
    const int tid = threadIdx.x, wid = tid >> 5, lane = tid & 31;
    const int wm = wid & 3, wn = wid >> 2;      // 4 along M x 4 along N; warp tile 32x32 (C & G)
    const int g  = lane >> 2, t4 = lane & 3;
    const int rowBase = blockIdx.y * BM;
    const int colBase = blockIdx.x * BN;

    const __half* actT = g_act + (size_t)blockIdx.y * (128 * 4096);
    const __half* wT   = g_wt  + (size_t)blockIdx.x * (128 * 8192);

    if (tid == 0) {
        for (int s = 0; s < NSTAGES; s++) mbar_init(sb + SM_MBAR + s * 8, 1);
    }
    __syncthreads();

    auto issue = [&](int ks) {
        uint32_t mb  = sb + SM_MBAR + (ks % NSTAGES) * 8;
        uint32_t dst = sb + SM_STAGE0 + (ks % NSTAGES) * STAGE_BYTES;
        mbar_expect_tx(mb, STAGE_BYTES);
        bulk_g2s(dst,                actT + (size_t)ks * 4096, A_TILE_BYTES, mb);
        bulk_g2s(dst + A_TILE_BYTES, wT   + (size_t)ks * 8192, B_TILE_BYTES, mb);
    };

    if (tid == 0) {
        FENCE_PROXY_ASYNC();
        for (int s = 0; s < 4; s++) issue(s);    // 4-deep prologue; quads refill to 8
    }

    float accC[2][4][4];     // [mt][nt][frag]
    float accG[2][4][4];
    #pragma unroll
    for (int a = 0; a < 2; a++)
        #pragma unroll
        for (int b = 0; b < 4; b++)
            #pragma unroll
            for (int c = 0; c < 4; c++) { accC[a][b][c] = 0.f; accG[a][b][c] = 0.f; }

    auto consume = [&](int kt) {
        const char* st = smem + SM_STAGE0 + (kt % NSTAGES) * STAGE_BYTES;
        #pragma unroll
        for (int kk = 0; kk < 2; kk++) {
            // A: 16-row blocks wm*2 + mt, each block = 32 granules (512B)
            const uint4* pA = (const uint4*)(st + kk * 4096 + wm * 1024 + lane * 16);
            uint4 VA[2];
            VA[0] = pA[0]; VA[1] = pA[32];

            const uint4* pC = (const uint4*)(st + A_TILE_BYTES + kk * 4096
                                             + wn * 1024 + lane * 16);
            const uint4* pG = (const uint4*)(st + A_TILE_BYTES + 8192 + kk * 4096
                                             + wn * 1024 + lane * 16);
            uint4 VC[2], VG[2];
            VC[0] = pC[0]; VC[1] = pC[32];
            VG[0] = pG[0]; VG[1] = pG[32];

            #pragma unroll
            for (int cc = 0; cc < 2; cc++) {
                #pragma unroll
                for (int mt = 0; mt < 2; mt++) {
                    // a0 = row g k-lo, a1 = row g+8 k-lo, a2 = row g k-hi, a3 = row g+8 k-hi
                    mma16(accC[mt][2 * cc],     VA[mt].x, VA[mt].z, VA[mt].y, VA[mt].w,
                          VC[cc].x, VC[cc].y);
                    mma16(accC[mt][2 * cc + 1], VA[mt].x, VA[mt].z, VA[mt].y, VA[mt].w,
                          VC[cc].z, VC[cc].w);
                    mma16(accG[mt][2 * cc],     VA[mt].x, VA[mt].z, VA[mt].y, VA[mt].w,
                          VG[cc].x, VG[cc].y);
                    mma16(accG[mt][2 * cc + 1], VA[mt].x, VA[mt].z, VA[mt].y, VA[mt].w,
                          VG[cc].z, VG[cc].w);
                }
            }
        }
    };

    auto wait_stage = [&](int ks) {
        mbar_wait(sb + SM_MBAR + (ks % NSTAGES) * 8, (uint32_t)((ks >> 3) & 1));
    };

    for (int kt = 0; kt < NITER; kt += 4) {
        __syncthreads();                        // all warps done with quad kt-4..kt-1
        if (tid == 0) {
            FENCE_PROXY_ASYNC();
            #pragma unroll
            for (int i = 4; i < 8; i++)         // slots (kt-4..kt-1)%8: consumed before sync
                if (kt + i < NITER) issue(kt + i);
        }
        // skewed waits: stage kt+i+1's wait runs before consume(kt+i) finishes issuing
        wait_stage(kt);
        #pragma unroll
        for (int i = 0; i < 4; i++) {
            if (i < 3) wait_stage(kt + i + 1);
            consume(kt + i);
        }
    }

    // Epilogue: h = alpha*state + (1-alpha)*sigmoid(zg)*tanh(zc), stored fp16
    #pragma unroll
    for (int nt = 0; nt < 4; nt++) {
        int j0 = colBase + wn * 32 + nt * 8 + 2 * t4;
        float bc0 = bc[j0],  bc1 = bc[j0 + 1];
        float bg0 = bg[j0],  bg1 = bg[j0 + 1];
        float al0 = expf(-expf(-log_step[j0]));      // alpha = exp(-1/exp(log_step))
        float al1 = expf(-expf(-log_step[j0 + 1]));
        #pragma unroll
        for (int mt = 0; mt < 2; mt++) {
            int r0 = rowBase + wm * 32 + mt * 16 + g;
            #pragma unroll
            for (int half = 0; half < 2; half++) {
                int r = r0 + half * 8;
                float zc0 = accC[mt][nt][half * 2]     + bc0;
                float zc1 = accC[mt][nt][half * 2 + 1] + bc1;
                float zg0 = accG[mt][nt][half * 2]     + bg0;
                float zg1 = accG[mt][nt][half * 2 + 1] + bg1;
                float s0 = state[(size_t)r * H_DIM + j0];
                float s1 = state[(size_t)r * H_DIM + j0 + 1];
                float cand0 = tanhf(zc0), cand1 = tanhf(zc1);
                float gate0 = 1.f / (1.f + expf(-zg0));
                float gate1 = 1.f / (1.f + expf(-zg1));
                float h0 = al0 * s0 + (1.f - al0) * gate0 * cand0;
                float h1 = al1 * s1 + (1.f - al1) * gate1 * cand1;
                *(__half2*)&g_h16[(size_t)r * H_DIM + j0] = __floats2half2_rn(h0, h1);
            }
        }
    }
}

// ---------------------------------------------------------------- layernorm over H=2048 (fp16 in, fp32 out)
__device__ __forceinline__ float warp_sum(float v) {
    #pragma unroll
    for (int o = 16; o; o >>= 1) v += __shfl_xor_sync(0xffffffffu, v, o);
    return v;
}

__global__ void ln_kernel(const float* __restrict__ gamma, const float* __restrict__ beta,
                          float* __restrict__ out)
{
    int row = blockIdx.x;
    int tid = threadIdx.x;                       // 256 threads, 8 halves each

    uint4 v = ((const uint4*)(g_h16 + (size_t)row * H_DIM))[tid];
    const __half2* hp = (const __half2*)&v;
    float f[8];
    #pragma unroll
    for (int i = 0; i < 4; i++) {
        float2 p = __half22float2(hp[i]);
        f[2 * i] = p.x; f[2 * i + 1] = p.y;
    }

    float s = 0.f, sq = 0.f;
    #pragma unroll
    for (int i = 0; i < 8; i++) { s += f[i]; sq += f[i] * f[i]; }

    s  = warp_sum(s);
    sq = warp_sum(sq);
    __shared__ float sh[16];
    int wid = tid >> 5, lane = tid & 31;
    if (lane == 0) { sh[wid] = s; sh[8 + wid] = sq; }
    __syncthreads();
    float tot = 0.f, totq = 0.f;
    #pragma unroll
    for (int i = 0; i < 8; i++) { tot += sh[i]; totq += sh[8 + i]; }

    float mu  = tot * (1.f / H_DIM);
    float var = totq * (1.f / H_DIM) - mu * mu;
    float inv = rsqrtf(var + 1e-5f);

    const float4* gm = (const float4*)(gamma + tid * 8);
    const float4* bt = (const float4*)(beta  + tid * 8);
    float4* o = (float4*)(out + (size_t)row * H_DIM + tid * 8);
    #pragma unroll
    for (int q = 0; q < 2; q++) {
        float4 gv = gm[q], bv = bt[q], ov;
        ov.x = (f[4 * q]     - mu) * inv * gv.x + bv.x;
        ov.y = (f[4 * q + 1] - mu) * inv * gv.y + bv.y;
        ov.z = (f[4 * q + 2] - mu) * inv * gv.z + bv.z;
        ov.w = (f[4 * q + 3] - mu) * inv * gv.w + bv.w;
        o[q] = ov;
    }
}

// ---------------------------------------------------------------- launch
extern "C" void kernel_launch(void* const* d_in, const int* in_sizes, int n_in,
                              void* d_out, int out_size) {
    const float* x_t      = (const float*)d_in[0];
    const float* state    = (const float*)d_in[1];
    const float* Wc       = (const float*)d_in[2];
    const float* Uc       = (const float*)d_in[3];
    const float* bc       = (const float*)d_in[4];
    const float* Wg       = (const float*)d_in[5];
    const float* Ug       = (const float*)d_in[6];
    const float* bg       = (const float*)d_in[7];
    const float* log_step = (const float*)d_in[8];
    const float* gamma    = (const float*)d_in[9];
    const float* beta     = (const float*)d_in[10];
    float* out = (float*)d_out;

    cudaFuncSetAttribute(gemm_kernel, cudaFuncAttributeMaxDynamicSharedMemorySize, SMEM_TOTAL);

    prep_all<<<8192 + 2048, 256>>>(x_t, state, Wc, Uc, Wg, Ug);

    dim3 grid(H_DIM / BN, B_DIM / BM);     // (16, 64) = 1024 CTAs
    gemm_kernel<<<grid, NTHREADS, SMEM_TOTAL>>>(state, bc, bg, log_step);

    ln_kernel<<<B_DIM, 256>>>(gamma, beta, out);
}

// round 17
// speedup vs baseline: 1.0864x; 1.0026x over previous
#include <cuda_runtime.h>
#include <cuda_fp16.h>
#include <cstdint>
#include <math.h>

// ---------------------------------------------------------------- dims
#define B_DIM 8192
#define H_DIM 2048
constexpr int KTOT = 4096;            // folded K: 2048 (x_t) + 2048 (state)

// GEMM tiling (fp16 operands, fp32 accumulate)
constexpr int BM = 128;               // batch rows per CTA
constexpr int BN = 128;               // H cols per CTA (cand & gate both)
constexpr int BK = 32;                // k per stage
constexpr int NSTAGES = 8;
constexpr int NITER = KTOT / BK;      // 128
constexpr int NTHREADS = 512;         // 16 warps: wm = wid&3 (4 along M), wn = wid>>2 (4 along N)

// Tile blob sizes (fragment-ordered, contiguous)
constexpr int A_TILE_BYTES = 8192;    // 128 rows x 32 k x fp16
constexpr int B_TILE_BYTES = 16384;   // (cand 128 + gate 128) cols x 32 k x fp16
constexpr int STAGE_BYTES  = A_TILE_BYTES + B_TILE_BYTES;   // 24576

// smem layout
constexpr int SM_MBAR   = 0;          // 8 x 8B mbarriers
constexpr int SM_STAGE0 = 1024;
constexpr int SMEM_TOTAL = SM_STAGE0 + NSTAGES * STAGE_BYTES;   // 197632

// k-permutation note: within each k16 mma block, thread t4 owns the CONTIGUOUS
// k quad {4t4..4t4+3} (applied identically to A and B fragments — dot products
// are permutation-invariant, so accumulators are bit-identical to natural order).
// Granule (16B): .x = rows r   k{4t4,4t4+1}, .y = row r   k{4t4+2,4t4+3},
//                .z = row r+8 same lo pair, .w = row r+8 same hi pair.
// Consumer passes (.x, .z, .y, .w) as (a0,a1,a2,a3) — unchanged.

// ---------------------------------------------------------------- scratch (device globals)
// Activations, tiled fragment-order: [rb(64)][ks(128)] -> 8KB blob
__device__ __align__(128) __half g_act[(size_t)64 * 128 * 4096];
// Weights (folded W+U), tiled fragment-order: [cb(16)][ks(128)] -> 16KB blob (Bc 8KB || Bg 8KB)
__device__ __align__(128) __half g_wt [(size_t)16 * 128 * 8192];
__device__ __align__(128) __half g_h16[(size_t)B_DIM * H_DIM];  // h_new (fp16) before layernorm

// ---------------------------------------------------------------- PTX helpers
__device__ __forceinline__ uint32_t smem_u32(const void* p) {
    uint32_t a;
    asm("{ .reg .u64 t; cvta.to.shared.u64 t, %1; cvt.u32.u64 %0, t; }" : "=r"(a) : "l"(p));
    return a;
}
__device__ __forceinline__ void mbar_init(uint32_t a, uint32_t cnt) {
    asm volatile("mbarrier.init.shared.b64 [%0], %1;" :: "r"(a), "r"(cnt) : "memory");
}
__device__ __forceinline__ void mbar_expect_tx(uint32_t a, uint32_t bytes) {
    asm volatile("mbarrier.arrive.expect_tx.shared.b64 _, [%0], %1;"
                 :: "r"(a), "r"(bytes) : "memory");
}
__device__ __forceinline__ void mbar_wait(uint32_t a, uint32_t parity) {
    asm volatile(
        "{\n\t.reg .pred P;\n\t"
        "WL_%=:\n\t"
        "mbarrier.try_wait.parity.acquire.cta.shared::cta.b64 P, [%0], %1, 0x989680;\n\t"
        "@!P bra WL_%=;\n\t}"
        :: "r"(a), "r"(parity) : "memory");
}
__device__ __forceinline__ void bulk_g2s(uint32_t dst_s, const void* src, uint32_t bytes,
                                         uint32_t mbar) {
    asm volatile(
        "cp.async.bulk.shared::cluster.global.mbarrier::complete_tx::bytes [%0], [%1], %2, [%3];"
        :: "r"(dst_s), "l"(src), "r"(bytes), "r"(mbar) : "memory");
}
#define FENCE_PROXY_ASYNC() asm volatile("fence.proxy.async.shared::cta;" ::: "memory")
__device__ __forceinline__ void mma16(float* c, uint32_t a0, uint32_t a1, uint32_t a2, uint32_t a3,
                                      uint32_t b0, uint32_t b1) {
    asm volatile(
        "mma.sync.aligned.m16n8k16.row.col.f32.f16.f16.f32 "
        "{%0,%1,%2,%3}, {%4,%5,%6,%7}, {%8,%9}, {%0,%1,%2,%3};"
        : "+f"(c[0]), "+f"(c[1]), "+f"(c[2]), "+f"(c[3])
        : "r"(a0), "r"(a1), "r"(a2), "r"(a3), "r"(b0), "r"(b1));
}
__device__ __forceinline__ uint32_t packh2(__half lo, __half hi) {
    __half2 p = __halves2half2(lo, hi);
    return *(uint32_t*)&p;
}
__device__ __forceinline__ uint32_t f2h2(float lo, float hi) {
    __half2 p = __floats2half2_rn(lo, hi);
    return *(uint32_t*)&p;
}

// ---------------------------------------------------------------- fused prep
// bid < 8192: activation tile (ks = bid&127, rb = bid>>7) -> 8KB fragment-ordered blob,
//   built DIRECTLY from global: per granule, 2x LDG.128 (rows r and r+8, k quad 4t4).
//   granule gi (16B) = [kk(2)][blk(8)][lane(32)]; lane=4g+t4; r = blk*16 + g
// bid >= 8192: weight tile (ks = b&127, cb = b>>7) -> 16KB blob: Bc (8KB) then Bg (8KB)
//   granule gi = [kk(2)][wn(4)][cc(2)][lane(32)]; j_lo = wn*32 + cc*16 + g; j_hi = j_lo+8
//   b0 = cols j, k{4t4,4t4+1}; b1 = k{4t4+2,4t4+3}
__global__ void prep_all(const float* __restrict__ x_t, const float* __restrict__ state,
                         const float* __restrict__ Wc, const float* __restrict__ Uc,
                         const float* __restrict__ Wg, const float* __restrict__ Ug) {
    __shared__ __half sm[8192];       // weights only
    const int bid = blockIdx.x;
    const int t = threadIdx.x;

    if (bid < 8192) {
        // ------------- activation tile: direct global -> fragment order -------------
        const int ks = bid & 127, rb = bid >> 7;
        const float* src = (ks < 64) ? x_t : state;
        const int ka = (ks & 63) * 32;

        uint4* dst = (uint4*)(g_act + ((size_t)rb * 128 + ks) * 4096);
        #pragma unroll
        for (int i = 0; i < 2; i++) {
            int gi = t + i * 256;
            int kk = gi >> 8, rem = gi & 255;
            int blk = rem >> 5, lane = rem & 31;
            int g = lane >> 2, t4 = lane & 3;
            int r  = rb * 128 + blk * 16 + g;
            int k  = ka + kk * 16 + 4 * t4;                        // contiguous k quad
            float4 v0 = *(const float4*)(src + (size_t)r * H_DIM + k);        // row r
            float4 v1 = *(const float4*)(src + (size_t)(r + 8) * H_DIM + k);  // row r+8
            dst[gi] = make_uint4(f2h2(v0.x, v0.y), f2h2(v0.z, v0.w),
                                 f2h2(v1.x, v1.y), f2h2(v1.z, v1.w));
        }
    } else {
        // ------------- weight tile (smem staging: fold + transpose-gather) -------------
        const int b = bid - 8192;
        const int ks = b & 127, cb = b >> 7;
        const int k0 = ks * 32, j0 = cb * 128;
        __half* smc = sm;            // [k(32)][j(128)]
        __half* smg = sm + 4096;

        {   // load 32 k-rows x 128 j, fold U, -> fp16 smem
            int kr = t >> 3, jq = (t & 7) * 16;
            int kg = k0 + kr;
            const float4* wc4 = (const float4*)(Wc + (size_t)kg * H_DIM + j0 + jq);
            const float4* wg4 = (const float4*)(Wg + (size_t)kg * H_DIM + j0 + jq);
            bool fold = (kg >= H_DIM);
            const float4* uc4 = (const float4*)(Uc + (size_t)(kg - H_DIM) * H_DIM + j0 + jq);
            const float4* ug4 = (const float4*)(Ug + (size_t)(kg - H_DIM) * H_DIM + j0 + jq);
            #pragma unroll
            for (int q = 0; q < 4; q++) {
                float4 a = wc4[q], bb = wg4[q];
                if (fold) {
                    float4 u = uc4[q], v = ug4[q];
                    a.x += u.x; a.y += u.y; a.z += u.z; a.w += u.w;
                    bb.x += v.x; bb.y += v.y; bb.z += v.z; bb.w += v.w;
                }
                __half2* dc = (__half2*)&smc[kr * 128 + jq + q * 4];
                __half2* dg = (__half2*)&smg[kr * 128 + jq + q * 4];
                dc[0] = __floats2half2_rn(a.x, a.y);  dc[1] = __floats2half2_rn(a.z, a.w);
                dg[0] = __floats2half2_rn(bb.x, bb.y); dg[1] = __floats2half2_rn(bb.z, bb.w);
            }
        }
        __syncthreads();

        uint4* dst = (uint4*)(g_wt + ((size_t)cb * 128 + ks) * 8192);
        #pragma unroll
        for (int i = 0; i < 4; i++) {
            int gi = t + i * 256;                       // 0..1023
            int m  = gi >> 9, rem = gi & 511;
            int kk = rem >> 8, wn = (rem >> 6) & 3, cc = (rem >> 5) & 1, lane = rem & 31;
            int g = lane >> 2, t4 = lane & 3;
            const __half* s = m ? smg : smc;
            int jlo = wn * 32 + cc * 16 + g;
            int jhi = jlo + 8;
            int kb  = kk * 16 + 4 * t4;                 // contiguous k quad
            uint32_t e01 = packh2(s[kb * 128 + jlo],       s[(kb + 1) * 128 + jlo]);
            uint32_t e23 = packh2(s[(kb + 2) * 128 + jlo], s[(kb + 3) * 128 + jlo]);
            uint32_t e45 = packh2(s[kb * 128 + jhi],       s[(kb + 1) * 128 + jhi]);
            uint32_t e67 = packh2(s[(kb + 2) * 128 + jhi], s[(kb + 3) * 128 + jhi]);
            dst[gi] = make_uint4(e01, e23, e45, e67);
        }
    }
}

// ---------------------------------------------------------------- main GEMM (16 warps, quad-batched)
__global__ void __launch_bounds__(NTHREADS, 1)
gemm_kernel(const float* __restrict__ state,
            const float* __restrict__ bc,  const float* __restrict__ bg,
            const float* __restrict__ log_step)
{
    extern __shared__ char smem[];
    const uint32_t sb = smem_u32(smem);
    const int tid = threadIdx.x, wid = tid >> 5, lane = tid & 31;
    const int wm = wid & 3, wn = wid >> 2;      // 4 along M x 4 along N; warp tile 32x32 (C & G)
    const int g  = lane >> 2, t4 = lane & 3;
    const int rowBase = blockIdx.y * BM;
    const int colBase = blockIdx.x * BN;

    const __half* actT = g_act + (size_t)blockIdx.y * (128 * 4096);
    const __half* wT   = g_wt  + (size_t)blockIdx.x * (128 * 8192);

    if (tid == 0) {
        for (int s = 0; s < NSTAGES; s++) mbar_init(sb + SM_MBAR + s * 8, 1);
    }
    __syncthreads();

    auto issue = [&](int ks) {
        uint32_t mb  = sb + SM_MBAR + (ks % NSTAGES) * 8;
        uint32_t dst = sb + SM_STAGE0 + (ks % NSTAGES) * STAGE_BYTES;
        mbar_expect_tx(mb, STAGE_BYTES);
        bulk_g2s(dst,                actT + (size_t)ks * 4096, A_TILE_BYTES, mb);
        bulk_g2s(dst + A_TILE_BYTES, wT   + (size_t)ks * 8192, B_TILE_BYTES, mb);
    };

    if (tid == 0) {
        FENCE_PROXY_ASYNC();
        for (int s = 0; s < 4; s++) issue(s);    // 4-deep prologue; quads refill to 8
    }

    float accC[2][4][4];     // [mt][nt][frag]
    float accG[2][4][4];
    #pragma unroll
    for (int a = 0; a < 2; a++)
        #pragma unroll
        for (int b = 0; b < 4; b++)
            #pragma unroll
            for (int c = 0; c < 4; c++) { accC[a][b][c] = 0.f; accG[a][b][c] = 0.f; }

    auto consume = [&](int kt) {
        const char* st = smem + SM_STAGE0 + (kt % NSTAGES) * STAGE_BYTES;
        #pragma unroll
        for (int kk = 0; kk < 2; kk++) {
            // A: 16-row blocks wm*2 + mt, each block = 32 granules (512B)
            const uint4* pA = (const uint4*)(st + kk * 4096 + wm * 1024 + lane * 16);
            uint4 VA[2];
            VA[0] = pA[0]; VA[1] = pA[32];

            const uint4* pC = (const uint4*)(st + A_TILE_BYTES + kk * 4096
                                             + wn * 1024 + lane * 16);
            const uint4* pG = (const uint4*)(st + A_TILE_BYTES + 8192 + kk * 4096
                                             + wn * 1024 + lane * 16);
            uint4 VC[2], VG[2];
            VC[0] = pC[0]; VC[1] = pC[32];
            VG[0] = pG[0]; VG[1] = pG[32];

            #pragma unroll
            for (int cc = 0; cc < 2; cc++) {
                #pragma unroll
                for (int mt = 0; mt < 2; mt++) {
                    // a0 = row g k-lo pair, a1 = row g+8 k-lo, a2 = row g k-hi, a3 = row g+8 k-hi
                    mma16(accC[mt][2 * cc],     VA[mt].x, VA[mt].z, VA[mt].y, VA[mt].w,
                          VC[cc].x, VC[cc].y);
                    mma16(accC[mt][2 * cc + 1], VA[mt].x, VA[mt].z, VA[mt].y, VA[mt].w,
                          VC[cc].z, VC[cc].w);
                    mma16(accG[mt][2 * cc],     VA[mt].x, VA[mt].z, VA[mt].y, VA[mt].w,
                          VG[cc].x, VG[cc].y);
                    mma16(accG[mt][2 * cc + 1], VA[mt].x, VA[mt].z, VA[mt].y, VA[mt].w,
                          VG[cc].z, VG[cc].w);
                }
            }
        }
    };

    auto wait_stage = [&](int ks) {
        mbar_wait(sb + SM_MBAR + (ks % NSTAGES) * 8, (uint32_t)((ks >> 3) & 1));
    };

    for (int kt = 0; kt < NITER; kt += 4) {
        __syncthreads();                        // all warps done with quad kt-4..kt-1
        if (tid == 0) {
            FENCE_PROXY_ASYNC();
            #pragma unroll
            for (int i = 4; i < 8; i++)         // slots (kt-4..kt-1)%8: consumed before sync
                if (kt + i < NITER) issue(kt + i);
        }
        // skewed waits: stage kt+i+1's wait runs before consume(kt+i) finishes issuing
        wait_stage(kt);
        #pragma unroll
        for (int i = 0; i < 4; i++) {
            if (i < 3) wait_stage(kt + i + 1);
            consume(kt + i);
        }
    }

    // Epilogue: h = alpha*state + (1-alpha)*sigmoid(zg)*tanh(zc), stored fp16
    #pragma unroll
    for (int nt = 0; nt < 4; nt++) {
        int j0 = colBase + wn * 32 + nt * 8 + 2 * t4;
        float bc0 = bc[j0],  bc1 = bc[j0 + 1];
        float bg0 = bg[j0],  bg1 = bg[j0 + 1];
        float al0 = expf(-expf(-log_step[j0]));      // alpha = exp(-1/exp(log_step))
        float al1 = expf(-expf(-log_step[j0 + 1]));
        #pragma unroll
        for (int mt = 0; mt < 2; mt++) {
            int r0 = rowBase + wm * 32 + mt * 16 + g;
            #pragma unroll
            for (int half = 0; half < 2; half++) {
                int r = r0 + half * 8;
                float zc0 = accC[mt][nt][half * 2]     + bc0;
                float zc1 = accC[mt][nt][half * 2 + 1] + bc1;
                float zg0 = accG[mt][nt][half * 2]     + bg0;
                float zg1 = accG[mt][nt][half * 2 + 1] + bg1;
                float s0 = state[(size_t)r * H_DIM + j0];
                float s1 = state[(size_t)r * H_DIM + j0 + 1];
                float cand0 = tanhf(zc0), cand1 = tanhf(zc1);
                float gate0 = 1.f / (1.f + expf(-zg0));
                float gate1 = 1.f / (1.f + expf(-zg1));
                float h0 = al0 * s0 + (1.f - al0) * gate0 * cand0;
                float h1 = al1 * s1 + (1.f - al1) * gate1 * cand1;
                *(__half2*)&g_h16[(size_t)r * H_DIM + j0] = __floats2half2_rn(h0, h1);
            }
        }
    }
}

// ---------------------------------------------------------------- layernorm over H=2048 (fp16 in, fp32 out)
__device__ __forceinline__ float warp_sum(float v) {
    #pragma unroll
    for (int o = 16; o; o >>= 1) v += __shfl_xor_sync(0xffffffffu, v, o);
    return v;
}

__global__ void ln_kernel(const float* __restrict__ gamma, const float* __restrict__ beta,
                          float* __restrict__ out)
{
    int row = blockIdx.x;
    int tid = threadIdx.x;                       // 256 threads, 8 halves each

    uint4 v = ((const uint4*)(g_h16 + (size_t)row * H_DIM))[tid];
    const __half2* hp = (const __half2*)&v;
    float f[8];
    #pragma unroll
    for (int i = 0; i < 4; i++) {
        float2 p = __half22float2(hp[i]);
        f[2 * i] = p.x; f[2 * i + 1] = p.y;
    }

    float s = 0.f, sq = 0.f;
    #pragma unroll
    for (int i = 0; i < 8; i++) { s += f[i]; sq += f[i] * f[i]; }

    s  = warp_sum(s);
    sq = warp_sum(sq);
    __shared__ float sh[16];
    int wid = tid >> 5, lane = tid & 31;
    if (lane == 0) { sh[wid] = s; sh[8 + wid] = sq; }
    __syncthreads();
    float tot = 0.f, totq = 0.f;
    #pragma unroll
    for (int i = 0; i < 8; i++) { tot += sh[i]; totq += sh[8 + i]; }

    float mu  = tot * (1.f / H_DIM);
    float var = totq * (1.f / H_DIM) - mu * mu;
    float inv = rsqrtf(var + 1e-5f);

    const float4* gm = (const float4*)(gamma + tid * 8);
    const float4* bt = (const float4*)(beta  + tid * 8);
    float4* o = (float4*)(out + (size_t)row * H_DIM + tid * 8);
    #pragma unroll
    for (int q = 0; q < 2; q++) {
        float4 gv = gm[q], bv = bt[q], ov;
        ov.x = (f[4 * q]     - mu) * inv * gv.x + bv.x;
        ov.y = (f[4 * q + 1] - mu) * inv * gv.y + bv.y;
        ov.z = (f[4 * q + 2] - mu) * inv * gv.z + bv.z;
        ov.w = (f[4 * q + 3] - mu) * inv * gv.w + bv.w;
        o[q] = ov;
    }
}

// ---------------------------------------------------------------- launch
extern "C" void kernel_launch(void* const* d_in, const int* in_sizes, int n_in,
                              void* d_out, int out_size) {
    const float* x_t      = (const float*)d_in[0];
    const float* state    = (const float*)d_in[1];
    const float* Wc       = (const float*)d_in[2];
    const float* Uc       = (const float*)d_in[3];
    const float* bc       = (const float*)d_in[4];
    const float* Wg       = (const float*)d_in[5];
    const float* Ug       = (const float*)d_in[6];
    const float* bg       = (const float*)d_in[7];
    const float* log_step = (const float*)d_in[8];
    const float* gamma    = (const float*)d_in[9];
    const float* beta     = (const float*)d_in[10];
    float* out = (float*)d_out;

    cudaFuncSetAttribute(gemm_kernel, cudaFuncAttributeMaxDynamicSharedMemorySize, SMEM_TOTAL);

    prep_all<<<8192 + 2048, 256>>>(x_t, state, Wc, Uc, Wg, Ug);

    dim3 grid(H_DIM / BN, B_DIM / BM);     // (16, 64) = 1024 CTAs
    gemm_kernel<<<grid, NTHREADS, SMEM_TOTAL>>>(state, bc, bg, log_step);

    ln_kernel<<<B_DIM, 256>>>(gamma, beta, out);
}